// round 12
// baseline (speedup 1.0000x reference)
#include <cuda_runtime.h>
#include <cuda_fp16.h>
#include <cstdint>

#define B_    4
#define S_    1024
#define H_    2048
#define E_    16
#define I_    2816
#define TOPK  8
#define T_    (B_ * S_)
#define GU_   (2 * I_)

// ---------------- device scratch ----------------
__device__ __half d_wgu16[(size_t)E_ * H_ * GU_];
__device__ __half d_wd16 [(size_t)E_ * I_ * H_];
__device__ __half d_x16  [(size_t)T_ * H_];
__device__ __half d_act  [(size_t)E_ * T_ * I_];
__device__ __half d_y    [(size_t)E_ * T_ * H_];
__device__ int    d_cnt[E_];
__device__ int    d_tok[E_][T_];
__device__ int    d_nsel[T_];
__device__ int    d_selrow[T_][TOPK];
__device__ float  d_selwt [T_][TOPK];

// ---------------- helpers ----------------
__device__ __forceinline__ uint32_t smem_u32(const void* p) {
    uint32_t a;
    asm("{ .reg .u64 t; cvta.to.shared.u64 t, %1; cvt.u32.u64 %0, t; }" : "=r"(a) : "l"(p));
    return a;
}
__device__ __forceinline__ void cp16(uint32_t dst, const void* src) {
    asm volatile("cp.async.cg.shared.global [%0], [%1], 16;" :: "r"(dst), "l"(src));
}
#define CP_COMMIT() asm volatile("cp.async.commit_group;" ::: "memory")
template <int N>
__device__ __forceinline__ void cp_wait() {
    asm volatile("cp.async.wait_group %0;" :: "n"(N) : "memory");
}
__device__ __forceinline__ void ldsm4(uint32_t* d, uint32_t addr) {
    asm volatile("ldmatrix.sync.aligned.m8n8.x4.shared.b16 {%0,%1,%2,%3}, [%4];"
        : "=r"(d[0]), "=r"(d[1]), "=r"(d[2]), "=r"(d[3]) : "r"(addr));
}
__device__ __forceinline__ void ldsm4t(uint32_t* d, uint32_t addr) {
    asm volatile("ldmatrix.sync.aligned.m8n8.x4.trans.shared.b16 {%0,%1,%2,%3}, [%4];"
        : "=r"(d[0]), "=r"(d[1]), "=r"(d[2]), "=r"(d[3]) : "r"(addr));
}
#define MMA16816(C, A, B0, B1)                                                 \
    asm volatile(                                                              \
        "mma.sync.aligned.m16n8k16.row.col.f32.f16.f16.f32 "                   \
        "{%0,%1,%2,%3}, {%4,%5,%6,%7}, {%8,%9}, {%0,%1,%2,%3};"                \
        : "+f"((C)[0]), "+f"((C)[1]), "+f"((C)[2]), "+f"((C)[3])               \
        : "r"((A)[0]), "r"((A)[1]), "r"((A)[2]), "r"((A)[3]), "r"(B0), "r"(B1))

#define SW(o) ((o) ^ (((o) >> 3) & 0x70))

// ---------------- small kernels ----------------
__global__ void convert_kernel(const float* __restrict__ src, __half2* __restrict__ dst,
                               size_t n4, int zero_cnt) {
    if (zero_cnt && blockIdx.x == 0 && threadIdx.x < E_) d_cnt[threadIdx.x] = 0;
    size_t i0 = (size_t)blockIdx.x * 512 + threadIdx.x;
    size_t i1 = i0 + 256;
    if (i1 < n4) {
        float4 v0 = reinterpret_cast<const float4*>(src)[i0];
        float4 v1 = reinterpret_cast<const float4*>(src)[i1];
        dst[2 * i0]     = __floats2half2_rn(v0.x, v0.y);
        dst[2 * i0 + 1] = __floats2half2_rn(v0.z, v0.w);
        dst[2 * i1]     = __floats2half2_rn(v1.x, v1.y);
        dst[2 * i1 + 1] = __floats2half2_rn(v1.z, v1.w);
    } else if (i0 < n4) {
        float4 v0 = reinterpret_cast<const float4*>(src)[i0];
        dst[2 * i0]     = __floats2half2_rn(v0.x, v0.y);
        dst[2 * i0 + 1] = __floats2half2_rn(v0.z, v0.w);
    }
}

__global__ void route_kernel(const void* __restrict__ idxp, const float* __restrict__ w) {
    __shared__ int s_is64;
    if (threadIdx.x == 0) {
        const int* p = (const int*)idxp;
        int all0 = 1;
        for (int i = 1; i < 256; i += 2) if (p[i] != 0) { all0 = 0; break; }
        s_is64 = all0;
    }
    __syncthreads();
    const int is64 = s_is64;
    int t = blockIdx.x * blockDim.x + threadIdx.x;
    if (t >= T_) return;
    float acc[E_];
#pragma unroll
    for (int e = 0; e < E_; e++) acc[e] = 0.f;
#pragma unroll
    for (int k = 0; k < TOPK; k++) {
        int e = is64 ? (int)((const long long*)idxp)[t * TOPK + k]
                     : ((const int*)idxp)[t * TOPK + k];
        if (e >= 0 && e < E_) acc[e] += w[t * TOPK + k];
    }
    int ns = 0;
#pragma unroll
    for (int e = 0; e < E_; e++) {
        if (acc[e] != 0.f) {
            int s = atomicAdd(&d_cnt[e], 1);
            d_tok[e][s] = t;
            d_selrow[t][ns] = e * T_ + s;
            d_selwt[t][ns]  = acc[e];
            ns++;
        }
    }
    d_nsel[t] = ns;
}

// ---------------------------------------------------------------------------
// GEMM1: act[e,row,n0:n0+64] = silu(X Wg) * (X Wu)
// BM=128, BN=64 act cols (128 weight cols), BK=64.
// 128 thr, 4 warps (2m x 2n), warp tile 64m x 32n-act dual accum (g,u).
// Fragment double-buffering: ldsm(ks+1) issued before MMAs(ks).
// ---------------------------------------------------------------------------
__global__ __launch_bounds__(128) void gemm1_kernel() {
    const int e = blockIdx.z, cnt = d_cnt[e];
    const int m0 = blockIdx.y * 128;
    if (m0 >= cnt) return;
    const int n0 = blockIdx.x * 64;

    extern __shared__ char dsm[];
    char* sm = (char*)(((uintptr_t)dsm + 1023) & ~(uintptr_t)1023);
    const uint32_t smb = smem_u32(sm);

    const int tid = threadIdx.x, lane = tid & 31, warp = tid >> 5;
    const int mw = (warp & 1) * 64;
    const int nv = warp >> 1;

    const int r0 = tid >> 3, ch = tid & 7;
    const uint32_t sa0 = SW((uint32_t)r0 * 128 + ch * 16);
    const __half* aptr[8];
#pragma unroll
    for (int j = 0; j < 8; j++) {
        int row = m0 + r0 + j * 16;
        int tok = d_tok[e][row < cnt ? row : cnt - 1];
        aptr[j] = d_x16 + (size_t)tok * H_ + ch * 8;
    }
    const __half* wb = d_wgu16 + (size_t)e * H_ * GU_;
    const __half* gbase = wb + n0 + ch * 8;
    const __half* ubase = wb + I_ + n0 + ch * 8;
    const uint32_t goff0 = (uint32_t)r0 * GU_;

    auto loadTile = [&](int s, int c) {
        uint32_t ab = smb + s * 32768;
        const size_t ka = (size_t)c * 64;
#pragma unroll
        for (int j = 0; j < 8; j++) cp16(ab + sa0 + j * 2048, aptr[j] + ka);
        const size_t kb = ka * GU_ + goff0;
#pragma unroll
        for (int j = 0; j < 4; j++) {
            uint32_t so = sa0 + j * 2048;
            cp16(ab + 16384 + so, gbase + kb + (size_t)j * 16 * GU_);
            cp16(ab + 24576 + so, ubase + kb + (size_t)j * 16 * GU_);
        }
    };

    float cg[4][4][4], cu[4][4][4];
#pragma unroll
    for (int mf = 0; mf < 4; mf++)
#pragma unroll
        for (int nf = 0; nf < 4; nf++)
#pragma unroll
            for (int q = 0; q < 4; q++) { cg[mf][nf][q] = 0.f; cu[mf][nf][q] = 0.f; }

    const int j8 = lane >> 3, r8 = lane & 7;

    uint32_t aAddr0[4];
#pragma unroll
    for (int mf = 0; mf < 4; mf++) {
        uint32_t row = (uint32_t)(mw + mf * 16 + (j8 & 1) * 8 + r8);
        uint32_t col0 = (uint32_t)((j8 >> 1) * 16);
        aAddr0[mf] = row * 128 + (col0 ^ ((row & 7) << 4));
    }
    const uint32_t bAddr0 = (uint32_t)((j8 & 1) * 8 + r8) * 128
                          + (((uint32_t)nv * 64 + (uint32_t)(j8 >> 1) * 16)
                             ^ ((uint32_t)r8 << 4));

    auto computeTile = [&](int s) {
        uint32_t ab = smb + s * 32768;
        uint32_t gb = ab + 16384, ub = ab + 24576;
        uint32_t a[2][4][4], bg[2][2][4], bu[2][2][4];
        // preload ks = 0
#pragma unroll
        for (int mf = 0; mf < 4; mf++) ldsm4(a[0][mf], ab + aAddr0[mf]);
#pragma unroll
        for (int nf2 = 0; nf2 < 2; nf2++) {
            uint32_t boff = bAddr0 ^ (nf2 << 5);
            ldsm4t(bg[0][nf2], gb + boff);
            ldsm4t(bu[0][nf2], ub + boff);
        }
#pragma unroll
        for (int ks = 0; ks < 4; ks++) {
            const int cur = ks & 1, nxt = cur ^ 1;
            if (ks < 3) {
#pragma unroll
                for (int mf = 0; mf < 4; mf++)
                    ldsm4(a[nxt][mf], ab + (aAddr0[mf] ^ ((ks + 1) << 5)));
                const uint32_t bk = bAddr0 + (ks + 1) * 2048;
#pragma unroll
                for (int nf2 = 0; nf2 < 2; nf2++) {
                    uint32_t boff = bk ^ (nf2 << 5);
                    ldsm4t(bg[nxt][nf2], gb + boff);
                    ldsm4t(bu[nxt][nf2], ub + boff);
                }
            }
#pragma unroll
            for (int nf2 = 0; nf2 < 2; nf2++) {
#pragma unroll
                for (int mf = 0; mf < 4; mf++) {
                    MMA16816(cg[mf][nf2 * 2 + 0], a[cur][mf], bg[cur][nf2][0], bg[cur][nf2][1]);
                    MMA16816(cg[mf][nf2 * 2 + 1], a[cur][mf], bg[cur][nf2][2], bg[cur][nf2][3]);
                    MMA16816(cu[mf][nf2 * 2 + 0], a[cur][mf], bu[cur][nf2][0], bu[cur][nf2][1]);
                    MMA16816(cu[mf][nf2 * 2 + 1], a[cur][mf], bu[cur][nf2][2], bu[cur][nf2][3]);
                }
            }
        }
    };

    const int NK = H_ / 64;  // 32
    loadTile(0, 0); CP_COMMIT();
    loadTile(1, 1); CP_COMMIT();
    int s = 0, sn = 2;
    for (int c = 0; c < NK; c++) {
        cp_wait<1>();
        __syncthreads();
        if (c + 2 < NK) loadTile(sn, c + 2);
        CP_COMMIT();
        computeTile(s);
        s = (s + 1 == 3) ? 0 : s + 1;
        sn = (sn + 1 == 3) ? 0 : sn + 1;
    }

    // epilogue: silu(g)*u -> fp16 act
#pragma unroll
    for (int mf = 0; mf < 4; mf++) {
#pragma unroll
        for (int h = 0; h < 2; h++) {
            int r = m0 + mw + mf * 16 + (lane >> 2) + h * 8;
            if (r >= cnt) continue;
            __half* actrow = d_act + ((size_t)e * T_ + r) * I_;
#pragma unroll
            for (int nf = 0; nf < 4; nf++) {
                int col = n0 + nv * 32 + nf * 8 + (lane & 3) * 2;
                float g0 = cg[mf][nf][h * 2 + 0], g1 = cg[mf][nf][h * 2 + 1];
                float u0 = cu[mf][nf][h * 2 + 0], u1 = cu[mf][nf][h * 2 + 1];
                float a0 = g0 / (1.f + __expf(-g0)) * u0;
                float a1 = g1 / (1.f + __expf(-g1)) * u1;
                *(__half2*)(actrow + col) = __floats2half2_rn(a0, a1);
            }
        }
    }
}

// ---------------------------------------------------------------------------
// GEMM2: y[e,row,n0:n0+128] = act_row @ Wd (fp16 out; combine applies w)
// BM=128, BN=128, BK=64. 128 thr, 4 warps (2m x 2n), warp tile 64x64.
// Fragment double-buffering as in GEMM1.
// ---------------------------------------------------------------------------
__global__ __launch_bounds__(128) void gemm2_kernel() {
    const int e = blockIdx.z, cnt = d_cnt[e];
    const int m0 = blockIdx.y * 128;
    if (m0 >= cnt) return;
    const int n0 = blockIdx.x * 128;

    extern __shared__ char dsm[];
    char* sm = (char*)(((uintptr_t)dsm + 1023) & ~(uintptr_t)1023);
    const uint32_t smb = smem_u32(sm);

    const int tid = threadIdx.x, lane = tid & 31, warp = tid >> 5;
    const int mw = (warp & 1) * 64;
    const int nv = warp >> 1;

    const int r0 = tid >> 3, ch = tid & 7;
    const uint32_t sa0 = SW((uint32_t)r0 * 128 + ch * 16);
    const __half* abase = d_act + ((size_t)e * T_ + m0) * I_ + (size_t)r0 * I_ + ch * 8;
    const __half* wbb = d_wd16 + (size_t)e * I_ * H_ + n0 + ch * 8;
    const uint32_t boff0 = (uint32_t)r0 * H_;

    auto loadTile = [&](int s, int c) {
        uint32_t ab = smb + s * 32768;
        const size_t ka = (size_t)c * 64;
#pragma unroll
        for (int j = 0; j < 8; j++)
            cp16(ab + sa0 + j * 2048, abase + (size_t)j * 16 * I_ + ka);
        const size_t kb = ka * H_ + boff0;
#pragma unroll
        for (int j = 0; j < 8; j++) {
            int p = j >> 2, jj = j & 3;
            cp16(ab + 16384 + p * 8192 + sa0 + jj * 2048,
                 wbb + kb + (size_t)jj * 16 * H_ + p * 64);
        }
    };

    float cc[4][8][4];
#pragma unroll
    for (int mf = 0; mf < 4; mf++)
#pragma unroll
        for (int nf = 0; nf < 8; nf++)
#pragma unroll
            for (int q = 0; q < 4; q++) cc[mf][nf][q] = 0.f;

    const int j8 = lane >> 3, r8 = lane & 7;

    uint32_t aAddr0[4];
#pragma unroll
    for (int mf = 0; mf < 4; mf++) {
        uint32_t row = (uint32_t)(mw + mf * 16 + (j8 & 1) * 8 + r8);
        uint32_t col0 = (uint32_t)((j8 >> 1) * 16);
        aAddr0[mf] = row * 128 + (col0 ^ ((row & 7) << 4));
    }
    const uint32_t bAddr0 = (uint32_t)nv * 8192
                          + (uint32_t)((j8 & 1) * 8 + r8) * 128
                          + (((uint32_t)(j8 >> 1) * 16) ^ ((uint32_t)r8 << 4));

    auto computeTile = [&](int s) {
        uint32_t ab = smb + s * 32768;
        uint32_t bb = ab + 16384;
        uint32_t a[2][4][4], b[2][4][4];
#pragma unroll
        for (int mf = 0; mf < 4; mf++) ldsm4(a[0][mf], ab + aAddr0[mf]);
#pragma unroll
        for (int nf2 = 0; nf2 < 4; nf2++)
            ldsm4t(b[0][nf2], bb + (bAddr0 ^ (nf2 << 5)));
#pragma unroll
        for (int ks = 0; ks < 4; ks++) {
            const int cur = ks & 1, nxt = cur ^ 1;
            if (ks < 3) {
#pragma unroll
                for (int mf = 0; mf < 4; mf++)
                    ldsm4(a[nxt][mf], ab + (aAddr0[mf] ^ ((ks + 1) << 5)));
                const uint32_t bk = bAddr0 + (ks + 1) * 2048;
#pragma unroll
                for (int nf2 = 0; nf2 < 4; nf2++)
                    ldsm4t(b[nxt][nf2], bb + (bk ^ (nf2 << 5)));
            }
#pragma unroll
            for (int nf2 = 0; nf2 < 4; nf2++) {
#pragma unroll
                for (int mf = 0; mf < 4; mf++) {
                    MMA16816(cc[mf][nf2 * 2 + 0], a[cur][mf], b[cur][nf2][0], b[cur][nf2][1]);
                    MMA16816(cc[mf][nf2 * 2 + 1], a[cur][mf], b[cur][nf2][2], b[cur][nf2][3]);
                }
            }
        }
    };

    const int NK = I_ / 64;  // 44
    loadTile(0, 0); CP_COMMIT();
    loadTile(1, 1); CP_COMMIT();
    int s = 0, sn = 2;
    for (int c = 0; c < NK; c++) {
        cp_wait<1>();
        __syncthreads();
        if (c + 2 < NK) loadTile(sn, c + 2);
        CP_COMMIT();
        computeTile(s);
        s = (s + 1 == 3) ? 0 : s + 1;
        sn = (sn + 1 == 3) ? 0 : sn + 1;
    }

#pragma unroll
    for (int mf = 0; mf < 4; mf++) {
#pragma unroll
        for (int h = 0; h < 2; h++) {
            int r = m0 + mw + mf * 16 + (lane >> 2) + h * 8;
            if (r >= cnt) continue;
            __half* yrow = d_y + ((size_t)e * T_ + r) * H_;
#pragma unroll
            for (int nf = 0; nf < 8; nf++) {
                int col = n0 + nv * 64 + nf * 8 + (lane & 3) * 2;
                *(__half2*)(yrow + col) = __floats2half2_rn(cc[mf][nf][h * 2 + 0],
                                                            cc[mf][nf][h * 2 + 1]);
            }
        }
    }
}

// ---------------- combine: out[t] = sum_j w_j * y[slot_j] ----------------
__global__ __launch_bounds__(256) void combine_kernel(float* __restrict__ out) {
    const int t = blockIdx.x;
    const int h0 = threadIdx.x * 8;
    float acc[8] = {0.f, 0.f, 0.f, 0.f, 0.f, 0.f, 0.f, 0.f};
    const int ns = d_nsel[t];
    for (int j = 0; j < ns; j++) {
        const float w = d_selwt[t][j];
        const __half2* p = (const __half2*)(d_y + (size_t)d_selrow[t][j] * H_ + h0);
#pragma unroll
        for (int q = 0; q < 4; q++) {
            float2 v = __half22float2(p[q]);
            acc[2 * q]     += w * v.x;
            acc[2 * q + 1] += w * v.y;
        }
    }
    float* o = out + (size_t)t * H_ + h0;
    *(float4*)o       = make_float4(acc[0], acc[1], acc[2], acc[3]);
    *(float4*)(o + 4) = make_float4(acc[4], acc[5], acc[6], acc[7]);
}

// ---------------- launch ----------------
extern "C" void kernel_launch(void* const* d_in, const int* in_sizes, int n_in,
                              void* d_out, int out_size) {
    const float* x    = (const float*)d_in[0];
    const float* wgu  = (const float*)d_in[1];
    const float* wd   = (const float*)d_in[2];
    const void*  eidx = d_in[3];
    const float* ew   = (const float*)d_in[4];
    float*       out  = (float*)d_out;

    __half2* wgu16_p; cudaGetSymbolAddress((void**)&wgu16_p, d_wgu16);
    __half2* wd16_p;  cudaGetSymbolAddress((void**)&wd16_p,  d_wd16);
    __half2* x16_p;   cudaGetSymbolAddress((void**)&x16_p,   d_x16);

    const int SMEM1 = 3 * 32768 + 1024;
    const int SMEM2 = 3 * 32768 + 1024;
    cudaFuncSetAttribute(gemm1_kernel, cudaFuncAttributeMaxDynamicSharedMemorySize, SMEM1);
    cudaFuncSetAttribute(gemm2_kernel, cudaFuncAttributeMaxDynamicSharedMemorySize, SMEM2);

    // Launch order keeps gemm1 as the 4th kernel (ncu capture slot).
    {
        size_t n4 = (size_t)E_ * H_ * GU_ / 4;
        convert_kernel<<<(unsigned)((n4 + 511) / 512), 256>>>(wgu, wgu16_p, n4, 1);
    }
    {
        size_t n4 = (size_t)T_ * H_ / 4;
        convert_kernel<<<(unsigned)((n4 + 511) / 512), 256>>>(x, x16_p, n4, 0);
    }
    route_kernel<<<T_ / 256, 256>>>(eidx, ew);
    gemm1_kernel<<<dim3(I_ / 64, T_ / 128, E_), 128, SMEM1>>>();
    {
        size_t n4 = (size_t)E_ * I_ * H_ / 4;
        convert_kernel<<<(unsigned)((n4 + 511) / 512), 256>>>(wd, wd16_p, n4, 0);
    }
    gemm2_kernel<<<dim3(H_ / 128, T_ / 128, E_), 128, SMEM2>>>();
    combine_kernel<<<T_, 256>>>(out);
}

// round 13
// speedup vs baseline: 1.0136x; 1.0136x over previous
#include <cuda_runtime.h>
#include <cuda_fp16.h>
#include <cstdint>

#define B_    4
#define S_    1024
#define H_    2048
#define E_    16
#define I_    2816
#define TOPK  8
#define T_    (B_ * S_)
#define GU_   (2 * I_)

// ---------------- device scratch ----------------
__device__ __half d_wgu16[(size_t)E_ * H_ * GU_];
__device__ __half d_wd16 [(size_t)E_ * I_ * H_];
__device__ __half d_x16  [(size_t)T_ * H_];
__device__ __half d_act  [(size_t)E_ * T_ * I_];
__device__ __half d_y    [(size_t)E_ * T_ * H_];
__device__ int    d_cnt[E_];
__device__ int    d_tok[E_][T_];
__device__ int    d_nsel[T_];
__device__ int    d_selrow[T_][TOPK];
__device__ float  d_selwt [T_][TOPK];

// ---------------- helpers ----------------
__device__ __forceinline__ uint32_t smem_u32(const void* p) {
    uint32_t a;
    asm("{ .reg .u64 t; cvta.to.shared.u64 t, %1; cvt.u32.u64 %0, t; }" : "=r"(a) : "l"(p));
    return a;
}
__device__ __forceinline__ void cp16(uint32_t dst, const void* src) {
    asm volatile("cp.async.cg.shared.global [%0], [%1], 16;" :: "r"(dst), "l"(src));
}
#define CP_COMMIT() asm volatile("cp.async.commit_group;" ::: "memory")
template <int N>
__device__ __forceinline__ void cp_wait() {
    asm volatile("cp.async.wait_group %0;" :: "n"(N) : "memory");
}
__device__ __forceinline__ void ldsm4(uint32_t* d, uint32_t addr) {
    asm volatile("ldmatrix.sync.aligned.m8n8.x4.shared.b16 {%0,%1,%2,%3}, [%4];"
        : "=r"(d[0]), "=r"(d[1]), "=r"(d[2]), "=r"(d[3]) : "r"(addr));
}
__device__ __forceinline__ void ldsm4t(uint32_t* d, uint32_t addr) {
    asm volatile("ldmatrix.sync.aligned.m8n8.x4.trans.shared.b16 {%0,%1,%2,%3}, [%4];"
        : "=r"(d[0]), "=r"(d[1]), "=r"(d[2]), "=r"(d[3]) : "r"(addr));
}
#define MMA16816(C, A, B0, B1)                                                 \
    asm volatile(                                                              \
        "mma.sync.aligned.m16n8k16.row.col.f32.f16.f16.f32 "                   \
        "{%0,%1,%2,%3}, {%4,%5,%6,%7}, {%8,%9}, {%0,%1,%2,%3};"                \
        : "+f"((C)[0]), "+f"((C)[1]), "+f"((C)[2]), "+f"((C)[3])               \
        : "r"((A)[0]), "r"((A)[1]), "r"((A)[2]), "r"((A)[3]), "r"(B0), "r"(B1))

#define SW(o) ((o) ^ (((o) >> 3) & 0x70))

// ---------------- small kernels ----------------
__global__ void convert_kernel(const float* __restrict__ src, __half2* __restrict__ dst,
                               size_t n4, int zero_cnt) {
    if (zero_cnt && blockIdx.x == 0 && threadIdx.x < E_) d_cnt[threadIdx.x] = 0;
    size_t i0 = (size_t)blockIdx.x * 512 + threadIdx.x;
    size_t i1 = i0 + 256;
    if (i1 < n4) {
        float4 v0 = reinterpret_cast<const float4*>(src)[i0];
        float4 v1 = reinterpret_cast<const float4*>(src)[i1];
        dst[2 * i0]     = __floats2half2_rn(v0.x, v0.y);
        dst[2 * i0 + 1] = __floats2half2_rn(v0.z, v0.w);
        dst[2 * i1]     = __floats2half2_rn(v1.x, v1.y);
        dst[2 * i1 + 1] = __floats2half2_rn(v1.z, v1.w);
    } else if (i0 < n4) {
        float4 v0 = reinterpret_cast<const float4*>(src)[i0];
        dst[2 * i0]     = __floats2half2_rn(v0.x, v0.y);
        dst[2 * i0 + 1] = __floats2half2_rn(v0.z, v0.w);
    }
}

__global__ void route_kernel(const void* __restrict__ idxp, const float* __restrict__ w) {
    __shared__ int s_is64;
    if (threadIdx.x == 0) {
        const int* p = (const int*)idxp;
        int all0 = 1;
        for (int i = 1; i < 256; i += 2) if (p[i] != 0) { all0 = 0; break; }
        s_is64 = all0;
    }
    __syncthreads();
    const int is64 = s_is64;
    int t = blockIdx.x * blockDim.x + threadIdx.x;
    if (t >= T_) return;
    float acc[E_];
#pragma unroll
    for (int e = 0; e < E_; e++) acc[e] = 0.f;
#pragma unroll
    for (int k = 0; k < TOPK; k++) {
        int e = is64 ? (int)((const long long*)idxp)[t * TOPK + k]
                     : ((const int*)idxp)[t * TOPK + k];
        if (e >= 0 && e < E_) acc[e] += w[t * TOPK + k];
    }
    int ns = 0;
#pragma unroll
    for (int e = 0; e < E_; e++) {
        if (acc[e] != 0.f) {
            int s = atomicAdd(&d_cnt[e], 1);
            d_tok[e][s] = t;
            d_selrow[t][ns] = e * T_ + s;
            d_selwt[t][ns]  = acc[e];
            ns++;
        }
    }
    d_nsel[t] = ns;
}

// ---------------------------------------------------------------------------
// GEMM1: act[e,row,n0:n0+64] = silu(X Wg) * (X Wu)
// BM=128, BN=64 act cols (128 weight cols), BK=64.
// 128 thr, 4 warps (2m x 2n), warp tile 64m x 32n-act dual accum (g,u).
// 3-stage cp.async; 2 CTAs/SM.
// ---------------------------------------------------------------------------
__global__ __launch_bounds__(128) void gemm1_kernel() {
    const int e = blockIdx.z, cnt = d_cnt[e];
    const int m0 = blockIdx.y * 128;
    if (m0 >= cnt) return;
    const int n0 = blockIdx.x * 64;

    extern __shared__ char dsm[];
    char* sm = (char*)(((uintptr_t)dsm + 1023) & ~(uintptr_t)1023);
    const uint32_t smb = smem_u32(sm);

    const int tid = threadIdx.x, lane = tid & 31, warp = tid >> 5;
    const int mw = (warp & 1) * 64;
    const int nv = warp >> 1;

    const int r0 = tid >> 3, ch = tid & 7;
    const uint32_t sa0 = SW((uint32_t)r0 * 128 + ch * 16);
    const __half* aptr[8];
#pragma unroll
    for (int j = 0; j < 8; j++) {
        int row = m0 + r0 + j * 16;
        int tok = d_tok[e][row < cnt ? row : cnt - 1];
        aptr[j] = d_x16 + (size_t)tok * H_ + ch * 8;
    }
    const __half* wb = d_wgu16 + (size_t)e * H_ * GU_;
    const __half* gbase = wb + n0 + ch * 8;
    const __half* ubase = wb + I_ + n0 + ch * 8;
    const uint32_t goff0 = (uint32_t)r0 * GU_;

    auto loadTile = [&](int s, int c) {
        uint32_t ab = smb + s * 32768;
        const size_t ka = (size_t)c * 64;
#pragma unroll
        for (int j = 0; j < 8; j++) cp16(ab + sa0 + j * 2048, aptr[j] + ka);
        const size_t kb = ka * GU_ + goff0;
#pragma unroll
        for (int j = 0; j < 4; j++) {
            uint32_t so = sa0 + j * 2048;
            cp16(ab + 16384 + so, gbase + kb + (size_t)j * 16 * GU_);
            cp16(ab + 24576 + so, ubase + kb + (size_t)j * 16 * GU_);
        }
    };

    float cg[4][4][4], cu[4][4][4];
#pragma unroll
    for (int mf = 0; mf < 4; mf++)
#pragma unroll
        for (int nf = 0; nf < 4; nf++)
#pragma unroll
            for (int q = 0; q < 4; q++) { cg[mf][nf][q] = 0.f; cu[mf][nf][q] = 0.f; }

    const int j8 = lane >> 3, r8 = lane & 7;

    uint32_t aAddr0[4];
#pragma unroll
    for (int mf = 0; mf < 4; mf++) {
        uint32_t row = (uint32_t)(mw + mf * 16 + (j8 & 1) * 8 + r8);
        uint32_t col0 = (uint32_t)((j8 >> 1) * 16);
        aAddr0[mf] = row * 128 + (col0 ^ ((row & 7) << 4));
    }
    const uint32_t bAddr0 = (uint32_t)((j8 & 1) * 8 + r8) * 128
                          + (((uint32_t)nv * 64 + (uint32_t)(j8 >> 1) * 16)
                             ^ ((uint32_t)r8 << 4));

    auto computeTile = [&](int s) {
        uint32_t ab = smb + s * 32768;
        uint32_t gb = ab + 16384, ub = ab + 24576;
#pragma unroll
        for (int ks = 0; ks < 4; ks++) {
            uint32_t a[4][4];
#pragma unroll
            for (int mf = 0; mf < 4; mf++)
                ldsm4(a[mf], ab + (aAddr0[mf] ^ (ks << 5)));
            const uint32_t bk = bAddr0 + ks * 2048;
#pragma unroll
            for (int nf2 = 0; nf2 < 2; nf2++) {
                uint32_t boff = bk ^ (nf2 << 5);
                uint32_t bg[4], bu[4];
                ldsm4t(bg, gb + boff);
                ldsm4t(bu, ub + boff);
#pragma unroll
                for (int mf = 0; mf < 4; mf++) {
                    MMA16816(cg[mf][nf2 * 2 + 0], a[mf], bg[0], bg[1]);
                    MMA16816(cg[mf][nf2 * 2 + 1], a[mf], bg[2], bg[3]);
                    MMA16816(cu[mf][nf2 * 2 + 0], a[mf], bu[0], bu[1]);
                    MMA16816(cu[mf][nf2 * 2 + 1], a[mf], bu[2], bu[3]);
                }
            }
        }
    };

    const int NK = H_ / 64;  // 32
    loadTile(0, 0); CP_COMMIT();
    loadTile(1, 1); CP_COMMIT();
    int s = 0, sn = 2;
    for (int c = 0; c < NK; c++) {
        cp_wait<1>();
        __syncthreads();
        if (c + 2 < NK) loadTile(sn, c + 2);
        CP_COMMIT();
        computeTile(s);
        s = (s + 1 == 3) ? 0 : s + 1;
        sn = (sn + 1 == 3) ? 0 : sn + 1;
    }

    // epilogue: silu(g)*u -> fp16 act
#pragma unroll
    for (int mf = 0; mf < 4; mf++) {
#pragma unroll
        for (int h = 0; h < 2; h++) {
            int r = m0 + mw + mf * 16 + (lane >> 2) + h * 8;
            if (r >= cnt) continue;
            __half* actrow = d_act + ((size_t)e * T_ + r) * I_;
#pragma unroll
            for (int nf = 0; nf < 4; nf++) {
                int col = n0 + nv * 32 + nf * 8 + (lane & 3) * 2;
                float g0 = cg[mf][nf][h * 2 + 0], g1 = cg[mf][nf][h * 2 + 1];
                float u0 = cu[mf][nf][h * 2 + 0], u1 = cu[mf][nf][h * 2 + 1];
                float a0 = g0 / (1.f + __expf(-g0)) * u0;
                float a1 = g1 / (1.f + __expf(-g1)) * u1;
                *(__half2*)(actrow + col) = __floats2half2_rn(a0, a1);
            }
        }
    }
}

// ---------------------------------------------------------------------------
// GEMM2: y[e,row,n0:n0+128] = act_row @ Wd (fp16 out; combine applies w)
// BM=128, BN=128, BK=64. 128 thr, 4 warps (2m x 2n), warp tile 64x64.
// ---------------------------------------------------------------------------
__global__ __launch_bounds__(128) void gemm2_kernel() {
    const int e = blockIdx.z, cnt = d_cnt[e];
    const int m0 = blockIdx.y * 128;
    if (m0 >= cnt) return;
    const int n0 = blockIdx.x * 128;

    extern __shared__ char dsm[];
    char* sm = (char*)(((uintptr_t)dsm + 1023) & ~(uintptr_t)1023);
    const uint32_t smb = smem_u32(sm);

    const int tid = threadIdx.x, lane = tid & 31, warp = tid >> 5;
    const int mw = (warp & 1) * 64;
    const int nv = warp >> 1;

    const int r0 = tid >> 3, ch = tid & 7;
    const uint32_t sa0 = SW((uint32_t)r0 * 128 + ch * 16);
    const __half* abase = d_act + ((size_t)e * T_ + m0) * I_ + (size_t)r0 * I_ + ch * 8;
    const __half* wbb = d_wd16 + (size_t)e * I_ * H_ + n0 + ch * 8;
    const uint32_t boff0 = (uint32_t)r0 * H_;

    auto loadTile = [&](int s, int c) {
        uint32_t ab = smb + s * 32768;
        const size_t ka = (size_t)c * 64;
#pragma unroll
        for (int j = 0; j < 8; j++)
            cp16(ab + sa0 + j * 2048, abase + (size_t)j * 16 * I_ + ka);
        const size_t kb = ka * H_ + boff0;
#pragma unroll
        for (int j = 0; j < 8; j++) {
            int p = j >> 2, jj = j & 3;
            cp16(ab + 16384 + p * 8192 + sa0 + jj * 2048,
                 wbb + kb + (size_t)jj * 16 * H_ + p * 64);
        }
    };

    float cc[4][8][4];
#pragma unroll
    for (int mf = 0; mf < 4; mf++)
#pragma unroll
        for (int nf = 0; nf < 8; nf++)
#pragma unroll
            for (int q = 0; q < 4; q++) cc[mf][nf][q] = 0.f;

    const int j8 = lane >> 3, r8 = lane & 7;

    uint32_t aAddr0[4];
#pragma unroll
    for (int mf = 0; mf < 4; mf++) {
        uint32_t row = (uint32_t)(mw + mf * 16 + (j8 & 1) * 8 + r8);
        uint32_t col0 = (uint32_t)((j8 >> 1) * 16);
        aAddr0[mf] = row * 128 + (col0 ^ ((row & 7) << 4));
    }
    const uint32_t bAddr0 = (uint32_t)nv * 8192
                          + (uint32_t)((j8 & 1) * 8 + r8) * 128
                          + (((uint32_t)(j8 >> 1) * 16) ^ ((uint32_t)r8 << 4));

    auto computeTile = [&](int s) {
        uint32_t ab = smb + s * 32768;
        uint32_t bb = ab + 16384;
#pragma unroll
        for (int ks = 0; ks < 4; ks++) {
            uint32_t a[4][4];
#pragma unroll
            for (int mf = 0; mf < 4; mf++)
                ldsm4(a[mf], ab + (aAddr0[mf] ^ (ks << 5)));
            const uint32_t bk = bAddr0 + ks * 2048;
#pragma unroll
            for (int nf2 = 0; nf2 < 4; nf2++) {
                uint32_t b[4];
                ldsm4t(b, bb + (bk ^ (nf2 << 5)));
#pragma unroll
                for (int mf = 0; mf < 4; mf++) {
                    MMA16816(cc[mf][nf2 * 2 + 0], a[mf], b[0], b[1]);
                    MMA16816(cc[mf][nf2 * 2 + 1], a[mf], b[2], b[3]);
                }
            }
        }
    };

    const int NK = I_ / 64;  // 44
    loadTile(0, 0); CP_COMMIT();
    loadTile(1, 1); CP_COMMIT();
    int s = 0, sn = 2;
    for (int c = 0; c < NK; c++) {
        cp_wait<1>();
        __syncthreads();
        if (c + 2 < NK) loadTile(sn, c + 2);
        CP_COMMIT();
        computeTile(s);
        s = (s + 1 == 3) ? 0 : s + 1;
        sn = (sn + 1 == 3) ? 0 : sn + 1;
    }

#pragma unroll
    for (int mf = 0; mf < 4; mf++) {
#pragma unroll
        for (int h = 0; h < 2; h++) {
            int r = m0 + mw + mf * 16 + (lane >> 2) + h * 8;
            if (r >= cnt) continue;
            __half* yrow = d_y + ((size_t)e * T_ + r) * H_;
#pragma unroll
            for (int nf = 0; nf < 8; nf++) {
                int col = n0 + nv * 64 + nf * 8 + (lane & 3) * 2;
                *(__half2*)(yrow + col) = __floats2half2_rn(cc[mf][nf][h * 2 + 0],
                                                            cc[mf][nf][h * 2 + 1]);
            }
        }
    }
}

// ---------------- combine: out[t] = sum_j w_j * y[slot_j] ----------------
__global__ __launch_bounds__(256) void combine_kernel(float* __restrict__ out) {
    const int t = blockIdx.x;
    const int h0 = threadIdx.x * 8;
    float acc[8] = {0.f, 0.f, 0.f, 0.f, 0.f, 0.f, 0.f, 0.f};
    const int ns = d_nsel[t];
    for (int j = 0; j < ns; j++) {
        const float w = d_selwt[t][j];
        const __half2* p = (const __half2*)(d_y + (size_t)d_selrow[t][j] * H_ + h0);
#pragma unroll
        for (int q = 0; q < 4; q++) {
            float2 v = __half22float2(p[q]);
            acc[2 * q]     += w * v.x;
            acc[2 * q + 1] += w * v.y;
        }
    }
    float* o = out + (size_t)t * H_ + h0;
    *(float4*)o       = make_float4(acc[0], acc[1], acc[2], acc[3]);
    *(float4*)(o + 4) = make_float4(acc[4], acc[5], acc[6], acc[7]);
}

// ---------------- launch ----------------
extern "C" void kernel_launch(void* const* d_in, const int* in_sizes, int n_in,
                              void* d_out, int out_size) {
    const float* x    = (const float*)d_in[0];
    const float* wgu  = (const float*)d_in[1];
    const float* wd   = (const float*)d_in[2];
    const void*  eidx = d_in[3];
    const float* ew   = (const float*)d_in[4];
    float*       out  = (float*)d_out;

    __half2* wgu16_p; cudaGetSymbolAddress((void**)&wgu16_p, d_wgu16);
    __half2* wd16_p;  cudaGetSymbolAddress((void**)&wd16_p,  d_wd16);
    __half2* x16_p;   cudaGetSymbolAddress((void**)&x16_p,   d_x16);

    const int SMEM1 = 3 * 32768 + 1024;
    const int SMEM2 = 3 * 32768 + 1024;
    cudaFuncSetAttribute(gemm1_kernel, cudaFuncAttributeMaxDynamicSharedMemorySize, SMEM1);
    cudaFuncSetAttribute(gemm2_kernel, cudaFuncAttributeMaxDynamicSharedMemorySize, SMEM2);

    // One-time host resources (created on the pre-capture correctness call;
    // no device memory, no work change — graph topology identical every capture).
    static cudaStream_t s2 = nullptr;
    static cudaEvent_t evFork = nullptr, evJoin = nullptr;
    if (s2 == nullptr) {
        cudaStreamCreateWithFlags(&s2, cudaStreamNonBlocking);
        cudaEventCreateWithFlags(&evFork, cudaEventDisableTiming);
        cudaEventCreateWithFlags(&evJoin, cudaEventDisableTiming);
    }

    // Fork: convert_wd runs on s2 concurrently with wgu/x converts + route + gemm1.
    cudaEventRecord(evFork, 0);
    cudaStreamWaitEvent(s2, evFork, 0);
    {
        size_t n4 = (size_t)E_ * I_ * H_ / 4;
        convert_kernel<<<(unsigned)((n4 + 511) / 512), 256, 0, s2>>>(wd, wd16_p, n4, 0);
    }
    cudaEventRecord(evJoin, s2);

    // Main stream: wgu convert (also zeros d_cnt), x convert, route, gemm1.
    {
        size_t n4 = (size_t)E_ * H_ * GU_ / 4;
        convert_kernel<<<(unsigned)((n4 + 511) / 512), 256>>>(wgu, wgu16_p, n4, 1);
    }
    {
        size_t n4 = (size_t)T_ * H_ / 4;
        convert_kernel<<<(unsigned)((n4 + 511) / 512), 256>>>(x, x16_p, n4, 0);
    }
    route_kernel<<<T_ / 256, 256>>>(eidx, ew);
    gemm1_kernel<<<dim3(I_ / 64, T_ / 128, E_), 128, SMEM1>>>();

    // Join: gemm2 needs convert_wd complete.
    cudaStreamWaitEvent(0, evJoin, 0);
    gemm2_kernel<<<dim3(H_ / 128, T_ / 128, E_), 128, SMEM2>>>();
    combine_kernel<<<T_, 256>>>(out);
}

// round 15
// speedup vs baseline: 1.0273x; 1.0135x over previous
#include <cuda_runtime.h>
#include <cuda_fp16.h>
#include <cstdint>

#define B_    4
#define S_    1024
#define H_    2048
#define E_    16
#define I_    2816
#define TOPK  8
#define T_    (B_ * S_)
#define GU_   (2 * I_)

// ---------------- device scratch ----------------
__device__ __half d_wgu16[(size_t)E_ * H_ * GU_];
__device__ __half d_wd16 [(size_t)E_ * I_ * H_];
__device__ __half d_x16  [(size_t)T_ * H_];
__device__ __half d_act  [(size_t)E_ * T_ * I_];
__device__ __half d_y    [(size_t)E_ * T_ * H_];
__device__ int    d_cnt[E_];
__device__ int    d_tok[E_][T_];
__device__ int    d_nsel[T_];
__device__ int    d_selrow[T_][TOPK];
__device__ float  d_selwt [T_][TOPK];

// ---------------- helpers ----------------
__device__ __forceinline__ uint32_t smem_u32(const void* p) {
    uint32_t a;
    asm("{ .reg .u64 t; cvta.to.shared.u64 t, %1; cvt.u32.u64 %0, t; }" : "=r"(a) : "l"(p));
    return a;
}
__device__ __forceinline__ void cp16(uint32_t dst, const void* src) {
    asm volatile("cp.async.cg.shared.global [%0], [%1], 16;" :: "r"(dst), "l"(src));
}
#define CP_COMMIT() asm volatile("cp.async.commit_group;" ::: "memory")
template <int N>
__device__ __forceinline__ void cp_wait() {
    asm volatile("cp.async.wait_group %0;" :: "n"(N) : "memory");
}
__device__ __forceinline__ void ldsm4(uint32_t* d, uint32_t addr) {
    asm volatile("ldmatrix.sync.aligned.m8n8.x4.shared.b16 {%0,%1,%2,%3}, [%4];"
        : "=r"(d[0]), "=r"(d[1]), "=r"(d[2]), "=r"(d[3]) : "r"(addr));
}
__device__ __forceinline__ void ldsm4t(uint32_t* d, uint32_t addr) {
    asm volatile("ldmatrix.sync.aligned.m8n8.x4.trans.shared.b16 {%0,%1,%2,%3}, [%4];"
        : "=r"(d[0]), "=r"(d[1]), "=r"(d[2]), "=r"(d[3]) : "r"(addr));
}
#define MMA16816(C, A, B0, B1)                                                 \
    asm volatile(                                                              \
        "mma.sync.aligned.m16n8k16.row.col.f32.f16.f16.f32 "                   \
        "{%0,%1,%2,%3}, {%4,%5,%6,%7}, {%8,%9}, {%0,%1,%2,%3};"                \
        : "+f"((C)[0]), "+f"((C)[1]), "+f"((C)[2]), "+f"((C)[3])               \
        : "r"((A)[0]), "r"((A)[1]), "r"((A)[2]), "r"((A)[3]), "r"(B0), "r"(B1))

#define SW(o) ((o) ^ (((o) >> 3) & 0x70))

// ---------------- small kernels ----------------
__global__ void convert_kernel(const float* __restrict__ src, __half2* __restrict__ dst,
                               size_t n4, int zero_cnt) {
    if (zero_cnt && blockIdx.x == 0 && threadIdx.x < E_) d_cnt[threadIdx.x] = 0;
    size_t i0 = (size_t)blockIdx.x * 512 + threadIdx.x;
    size_t i1 = i0 + 256;
    if (i1 < n4) {
        float4 v0 = reinterpret_cast<const float4*>(src)[i0];
        float4 v1 = reinterpret_cast<const float4*>(src)[i1];
        dst[2 * i0]     = __floats2half2_rn(v0.x, v0.y);
        dst[2 * i0 + 1] = __floats2half2_rn(v0.z, v0.w);
        dst[2 * i1]     = __floats2half2_rn(v1.x, v1.y);
        dst[2 * i1 + 1] = __floats2half2_rn(v1.z, v1.w);
    } else if (i0 < n4) {
        float4 v0 = reinterpret_cast<const float4*>(src)[i0];
        dst[2 * i0]     = __floats2half2_rn(v0.x, v0.y);
        dst[2 * i0 + 1] = __floats2half2_rn(v0.z, v0.w);
    }
}

__global__ void route_kernel(const void* __restrict__ idxp, const float* __restrict__ w) {
    __shared__ int s_is64;
    if (threadIdx.x == 0) {
        const int* p = (const int*)idxp;
        int all0 = 1;
        for (int i = 1; i < 256; i += 2) if (p[i] != 0) { all0 = 0; break; }
        s_is64 = all0;
    }
    __syncthreads();
    const int is64 = s_is64;
    int t = blockIdx.x * blockDim.x + threadIdx.x;
    if (t >= T_) return;
    float acc[E_];
#pragma unroll
    for (int e = 0; e < E_; e++) acc[e] = 0.f;
#pragma unroll
    for (int k = 0; k < TOPK; k++) {
        int e = is64 ? (int)((const long long*)idxp)[t * TOPK + k]
                     : ((const int*)idxp)[t * TOPK + k];
        if (e >= 0 && e < E_) acc[e] += w[t * TOPK + k];
    }
    int ns = 0;
#pragma unroll
    for (int e = 0; e < E_; e++) {
        if (acc[e] != 0.f) {
            int s = atomicAdd(&d_cnt[e], 1);
            d_tok[e][s] = t;
            d_selrow[t][ns] = e * T_ + s;
            d_selwt[t][ns]  = acc[e];
            ns++;
        }
    }
    d_nsel[t] = ns;
}

// ---------------------------------------------------------------------------
// GEMM1: act[e,row,n0:n0+64] = silu(X Wg) * (X Wu)
// BM=128, BN=64 act cols (128 weight cols), BK=64.
// 128 thr, 4 warps (2m x 2n), warp tile 64m x 32n-act dual accum (g,u).
// 3-stage cp.async; 2 CTAs/SM.
// ---------------------------------------------------------------------------
__global__ __launch_bounds__(128) void gemm1_kernel() {
    const int e = blockIdx.z, cnt = d_cnt[e];
    const int m0 = blockIdx.y * 128;
    if (m0 >= cnt) return;
    const int n0 = blockIdx.x * 64;

    extern __shared__ char dsm[];
    char* sm = (char*)(((uintptr_t)dsm + 1023) & ~(uintptr_t)1023);
    const uint32_t smb = smem_u32(sm);

    const int tid = threadIdx.x, lane = tid & 31, warp = tid >> 5;
    const int mw = (warp & 1) * 64;
    const int nv = warp >> 1;

    const int r0 = tid >> 3, ch = tid & 7;
    const uint32_t sa0 = SW((uint32_t)r0 * 128 + ch * 16);
    const __half* aptr[8];
#pragma unroll
    for (int j = 0; j < 8; j++) {
        int row = m0 + r0 + j * 16;
        int tok = d_tok[e][row < cnt ? row : cnt - 1];
        aptr[j] = d_x16 + (size_t)tok * H_ + ch * 8;
    }
    const __half* wb = d_wgu16 + (size_t)e * H_ * GU_;
    const __half* gbase = wb + n0 + ch * 8;
    const __half* ubase = wb + I_ + n0 + ch * 8;
    const uint32_t goff0 = (uint32_t)r0 * GU_;

    auto loadTile = [&](int s, int c) {
        uint32_t ab = smb + s * 32768;
        const size_t ka = (size_t)c * 64;
#pragma unroll
        for (int j = 0; j < 8; j++) cp16(ab + sa0 + j * 2048, aptr[j] + ka);
        const size_t kb = ka * GU_ + goff0;
#pragma unroll
        for (int j = 0; j < 4; j++) {
            uint32_t so = sa0 + j * 2048;
            cp16(ab + 16384 + so, gbase + kb + (size_t)j * 16 * GU_);
            cp16(ab + 24576 + so, ubase + kb + (size_t)j * 16 * GU_);
        }
    };

    float cg[4][4][4], cu[4][4][4];
#pragma unroll
    for (int mf = 0; mf < 4; mf++)
#pragma unroll
        for (int nf = 0; nf < 4; nf++)
#pragma unroll
            for (int q = 0; q < 4; q++) { cg[mf][nf][q] = 0.f; cu[mf][nf][q] = 0.f; }

    const int j8 = lane >> 3, r8 = lane & 7;

    uint32_t aAddr0[4];
#pragma unroll
    for (int mf = 0; mf < 4; mf++) {
        uint32_t row = (uint32_t)(mw + mf * 16 + (j8 & 1) * 8 + r8);
        uint32_t col0 = (uint32_t)((j8 >> 1) * 16);
        aAddr0[mf] = row * 128 + (col0 ^ ((row & 7) << 4));
    }
    const uint32_t bAddr0 = (uint32_t)((j8 & 1) * 8 + r8) * 128
                          + (((uint32_t)nv * 64 + (uint32_t)(j8 >> 1) * 16)
                             ^ ((uint32_t)r8 << 4));

    auto computeTile = [&](int s) {
        uint32_t ab = smb + s * 32768;
        uint32_t gb = ab + 16384, ub = ab + 24576;
#pragma unroll
        for (int ks = 0; ks < 4; ks++) {
            uint32_t a[4][4];
#pragma unroll
            for (int mf = 0; mf < 4; mf++)
                ldsm4(a[mf], ab + (aAddr0[mf] ^ (ks << 5)));
            const uint32_t bk = bAddr0 + ks * 2048;
#pragma unroll
            for (int nf2 = 0; nf2 < 2; nf2++) {
                uint32_t boff = bk ^ (nf2 << 5);
                uint32_t bg[4], bu[4];
                ldsm4t(bg, gb + boff);
                ldsm4t(bu, ub + boff);
#pragma unroll
                for (int mf = 0; mf < 4; mf++) {
                    MMA16816(cg[mf][nf2 * 2 + 0], a[mf], bg[0], bg[1]);
                    MMA16816(cg[mf][nf2 * 2 + 1], a[mf], bg[2], bg[3]);
                    MMA16816(cu[mf][nf2 * 2 + 0], a[mf], bu[0], bu[1]);
                    MMA16816(cu[mf][nf2 * 2 + 1], a[mf], bu[2], bu[3]);
                }
            }
        }
    };

    const int NK = H_ / 64;  // 32
    loadTile(0, 0); CP_COMMIT();
    loadTile(1, 1); CP_COMMIT();
    int s = 0, sn = 2;
    for (int c = 0; c < NK; c++) {
        cp_wait<1>();
        __syncthreads();
        if (c + 2 < NK) loadTile(sn, c + 2);
        CP_COMMIT();
        computeTile(s);
        s = (s + 1 == 3) ? 0 : s + 1;
        sn = (sn + 1 == 3) ? 0 : sn + 1;
    }

    // epilogue: silu(g)*u -> fp16 act
#pragma unroll
    for (int mf = 0; mf < 4; mf++) {
#pragma unroll
        for (int h = 0; h < 2; h++) {
            int r = m0 + mw + mf * 16 + (lane >> 2) + h * 8;
            if (r >= cnt) continue;
            __half* actrow = d_act + ((size_t)e * T_ + r) * I_;
#pragma unroll
            for (int nf = 0; nf < 4; nf++) {
                int col = n0 + nv * 32 + nf * 8 + (lane & 3) * 2;
                float g0 = cg[mf][nf][h * 2 + 0], g1 = cg[mf][nf][h * 2 + 1];
                float u0 = cu[mf][nf][h * 2 + 0], u1 = cu[mf][nf][h * 2 + 1];
                float a0 = g0 / (1.f + __expf(-g0)) * u0;
                float a1 = g1 / (1.f + __expf(-g1)) * u1;
                *(__half2*)(actrow + col) = __floats2half2_rn(a0, a1);
            }
        }
    }
}

// ---------------------------------------------------------------------------
// GEMM2: y[e,row,n0:n0+128] = act_row @ Wd (fp16 out; combine applies w)
// BM=128, BN=128, BK=64. 128 thr, 4 warps (2m x 2n), warp tile 64x64.
// ---------------------------------------------------------------------------
__global__ __launch_bounds__(128) void gemm2_kernel() {
    const int e = blockIdx.z, cnt = d_cnt[e];
    const int m0 = blockIdx.y * 128;
    if (m0 >= cnt) return;
    const int n0 = blockIdx.x * 128;

    extern __shared__ char dsm[];
    char* sm = (char*)(((uintptr_t)dsm + 1023) & ~(uintptr_t)1023);
    const uint32_t smb = smem_u32(sm);

    const int tid = threadIdx.x, lane = tid & 31, warp = tid >> 5;
    const int mw = (warp & 1) * 64;
    const int nv = warp >> 1;

    const int r0 = tid >> 3, ch = tid & 7;
    const uint32_t sa0 = SW((uint32_t)r0 * 128 + ch * 16);
    const __half* abase = d_act + ((size_t)e * T_ + m0) * I_ + (size_t)r0 * I_ + ch * 8;
    const __half* wbb = d_wd16 + (size_t)e * I_ * H_ + n0 + ch * 8;
    const uint32_t boff0 = (uint32_t)r0 * H_;

    auto loadTile = [&](int s, int c) {
        uint32_t ab = smb + s * 32768;
        const size_t ka = (size_t)c * 64;
#pragma unroll
        for (int j = 0; j < 8; j++)
            cp16(ab + sa0 + j * 2048, abase + (size_t)j * 16 * I_ + ka);
        const size_t kb = ka * H_ + boff0;
#pragma unroll
        for (int j = 0; j < 8; j++) {
            int p = j >> 2, jj = j & 3;
            cp16(ab + 16384 + p * 8192 + sa0 + jj * 2048,
                 wbb + kb + (size_t)jj * 16 * H_ + p * 64);
        }
    };

    float cc[4][8][4];
#pragma unroll
    for (int mf = 0; mf < 4; mf++)
#pragma unroll
        for (int nf = 0; nf < 8; nf++)
#pragma unroll
            for (int q = 0; q < 4; q++) cc[mf][nf][q] = 0.f;

    const int j8 = lane >> 3, r8 = lane & 7;

    uint32_t aAddr0[4];
#pragma unroll
    for (int mf = 0; mf < 4; mf++) {
        uint32_t row = (uint32_t)(mw + mf * 16 + (j8 & 1) * 8 + r8);
        uint32_t col0 = (uint32_t)((j8 >> 1) * 16);
        aAddr0[mf] = row * 128 + (col0 ^ ((row & 7) << 4));
    }
    const uint32_t bAddr0 = (uint32_t)nv * 8192
                          + (uint32_t)((j8 & 1) * 8 + r8) * 128
                          + (((uint32_t)(j8 >> 1) * 16) ^ ((uint32_t)r8 << 4));

    auto computeTile = [&](int s) {
        uint32_t ab = smb + s * 32768;
        uint32_t bb = ab + 16384;
#pragma unroll
        for (int ks = 0; ks < 4; ks++) {
            uint32_t a[4][4];
#pragma unroll
            for (int mf = 0; mf < 4; mf++)
                ldsm4(a[mf], ab + (aAddr0[mf] ^ (ks << 5)));
            const uint32_t bk = bAddr0 + ks * 2048;
#pragma unroll
            for (int nf2 = 0; nf2 < 4; nf2++) {
                uint32_t b[4];
                ldsm4t(b, bb + (bk ^ (nf2 << 5)));
#pragma unroll
                for (int mf = 0; mf < 4; mf++) {
                    MMA16816(cc[mf][nf2 * 2 + 0], a[mf], b[0], b[1]);
                    MMA16816(cc[mf][nf2 * 2 + 1], a[mf], b[2], b[3]);
                }
            }
        }
    };

    const int NK = I_ / 64;  // 44
    loadTile(0, 0); CP_COMMIT();
    loadTile(1, 1); CP_COMMIT();
    int s = 0, sn = 2;
    for (int c = 0; c < NK; c++) {
        cp_wait<1>();
        __syncthreads();
        if (c + 2 < NK) loadTile(sn, c + 2);
        CP_COMMIT();
        computeTile(s);
        s = (s + 1 == 3) ? 0 : s + 1;
        sn = (sn + 1 == 3) ? 0 : sn + 1;
    }

#pragma unroll
    for (int mf = 0; mf < 4; mf++) {
#pragma unroll
        for (int h = 0; h < 2; h++) {
            int r = m0 + mw + mf * 16 + (lane >> 2) + h * 8;
            if (r >= cnt) continue;
            __half* yrow = d_y + ((size_t)e * T_ + r) * H_;
#pragma unroll
            for (int nf = 0; nf < 8; nf++) {
                int col = n0 + nv * 64 + nf * 8 + (lane & 3) * 2;
                *(__half2*)(yrow + col) = __floats2half2_rn(cc[mf][nf][h * 2 + 0],
                                                            cc[mf][nf][h * 2 + 1]);
            }
        }
    }
}

// ---------------- combine: out[t] = sum_j w_j * y[slot_j] ----------------
__global__ __launch_bounds__(256) void combine_kernel(float* __restrict__ out) {
    const int t = blockIdx.x;
    const int h0 = threadIdx.x * 8;
    float acc[8] = {0.f, 0.f, 0.f, 0.f, 0.f, 0.f, 0.f, 0.f};
    const int ns = d_nsel[t];
    for (int j = 0; j < ns; j++) {
        const float w = d_selwt[t][j];
        const __half2* p = (const __half2*)(d_y + (size_t)d_selrow[t][j] * H_ + h0);
#pragma unroll
        for (int q = 0; q < 4; q++) {
            float2 v = __half22float2(p[q]);
            acc[2 * q]     += w * v.x;
            acc[2 * q + 1] += w * v.y;
        }
    }
    float* o = out + (size_t)t * H_ + h0;
    *(float4*)o       = make_float4(acc[0], acc[1], acc[2], acc[3]);
    *(float4*)(o + 4) = make_float4(acc[4], acc[5], acc[6], acc[7]);
}

// ---------------- launch ----------------
extern "C" void kernel_launch(void* const* d_in, const int* in_sizes, int n_in,
                              void* d_out, int out_size) {
    const float* x    = (const float*)d_in[0];
    const float* wgu  = (const float*)d_in[1];
    const float* wd   = (const float*)d_in[2];
    const void*  eidx = d_in[3];
    const float* ew   = (const float*)d_in[4];
    float*       out  = (float*)d_out;

    __half2* wgu16_p; cudaGetSymbolAddress((void**)&wgu16_p, d_wgu16);
    __half2* wd16_p;  cudaGetSymbolAddress((void**)&wd16_p,  d_wd16);
    __half2* x16_p;   cudaGetSymbolAddress((void**)&x16_p,   d_x16);

    const int SMEM1 = 3 * 32768 + 1024;
    const int SMEM2 = 3 * 32768 + 1024;
    cudaFuncSetAttribute(gemm1_kernel, cudaFuncAttributeMaxDynamicSharedMemorySize, SMEM1);
    cudaFuncSetAttribute(gemm2_kernel, cudaFuncAttributeMaxDynamicSharedMemorySize, SMEM2);

    static cudaStream_t s2 = nullptr;
    static cudaEvent_t evFork = nullptr, evRoute = nullptr, evWgu = nullptr, evJoin = nullptr;
    if (s2 == nullptr) {
        cudaStreamCreateWithFlags(&s2, cudaStreamNonBlocking);
        cudaEventCreateWithFlags(&evFork,  cudaEventDisableTiming);
        cudaEventCreateWithFlags(&evRoute, cudaEventDisableTiming);
        cudaEventCreateWithFlags(&evWgu,   cudaEventDisableTiming);
        cudaEventCreateWithFlags(&evJoin,  cudaEventDisableTiming);
    }

    // --- capture-legal host order: every wait follows its record ---

    // Fork s2 from main.
    cudaEventRecord(evFork, 0);
    cudaStreamWaitEvent(s2, evFork, 0);

    // s2: x convert (+zero d_cnt) -> route -> evRoute
    {
        size_t n4 = (size_t)T_ * H_ / 4;
        convert_kernel<<<(unsigned)((n4 + 511) / 512), 256, 0, s2>>>(x, x16_p, n4, 1);
    }
    route_kernel<<<T_ / 256, 256, 0, s2>>>(eidx, ew);
    cudaEventRecord(evRoute, s2);

    // main: wgu convert -> evWgu  (recorded BEFORE s2 waits on it)
    {
        size_t n4 = (size_t)E_ * H_ * GU_ / 4;
        convert_kernel<<<(unsigned)((n4 + 511) / 512), 256>>>(wgu, wgu16_p, n4, 0);
    }
    cudaEventRecord(evWgu, 0);

    // s2: wait wgu done, then wd convert (overlaps gemm1 on main) -> evJoin
    cudaStreamWaitEvent(s2, evWgu, 0);
    {
        size_t n4 = (size_t)E_ * I_ * H_ / 4;
        convert_kernel<<<(unsigned)((n4 + 511) / 512), 256, 0, s2>>>(wd, wd16_p, n4, 0);
    }
    cudaEventRecord(evJoin, s2);

    // main: gemm1 (needs route + x16), then gemm2 (needs wd16), combine.
    cudaStreamWaitEvent(0, evRoute, 0);
    gemm1_kernel<<<dim3(I_ / 64, T_ / 128, E_), 128, SMEM1>>>();
    cudaStreamWaitEvent(0, evJoin, 0);
    gemm2_kernel<<<dim3(H_ / 128, T_ / 128, E_), 128, SMEM2>>>();
    combine_kernel<<<T_, 256>>>(out);
}